// round 16
// baseline (speedup 1.0000x reference)
#include <cuda_runtime.h>
#include <cuda_bf16.h>
#include <cuda_fp16.h>
#include <mma.h>
#include <cstdint>

using namespace nvcuda;
typedef __nv_bfloat16 bf16;

#define DIM    512
#define NH     16
#define HD     32
#define NWIN   512      // 8 batches * 8*8 windows
#define NTOK   32768    // 512 windows * 64 tokens
#define NQKV   1536
#define WSCALE 0.17677669529663687f   // 32^-0.5

// GEMM tiling: 64x64 tile, 128 threads (4 warps of 32x32), BK=64,
// double-buffered, ONE barrier per k-tile. fp16 single-single, fp32 accum.
#define BM 64
#define BN 64
#define BK 64
#define SA 72    // A smem row stride (halves) — 144 B
#define SB 72    // B smem row stride (halves)
#define SC 68    // C epilogue stride (f32)
#define STAGE_B 18432          // bytes/stage: A 9216 + B 9216
#define STAGE_E 9216           // halves/stage
// attention smem stride
#define ASA 40

// Scratch (__device__ globals). RULE: referenced ONLY from device code.
// q/k planes: bf16 hi/lo (S uses bf16-3). v planes: fp16 hi/lo (AV uses fp16-2).
__device__ bf16   g_qh[(size_t)NWIN * NH * 64 * HD];
__device__ bf16   g_ql[(size_t)NWIN * NH * 64 * HD];
__device__ bf16   g_kh[(size_t)NWIN * NH * 64 * HD];
__device__ bf16   g_kl[(size_t)NWIN * NH * 64 * HD];
__device__ __half g_vh[(size_t)NWIN * NH * 64 * HD];
__device__ __half g_vl[(size_t)NWIN * NH * 64 * HD];
// fp16 single-precision operands (uint4 = 8 halves)
__device__ uint4 g_xh [(size_t)NTOK * DIM / 8];
__device__ uint4 g_aoh[(size_t)NTOK * DIM / 8];
__device__ uint4 g_wqh[(size_t)DIM * NQKV / 8];
__device__ uint4 g_wph[(size_t)DIM * DIM / 8];

__device__ __forceinline__ unsigned short ush(__half v) { return __half_as_ushort(v); }

__device__ __forceinline__ uint4 pack8_fp16(float4 v0, float4 v1) {
    uint4 o;
    o.x = ush(__float2half_rn(v0.x)) | ((unsigned)ush(__float2half_rn(v0.y)) << 16);
    o.y = ush(__float2half_rn(v0.z)) | ((unsigned)ush(__float2half_rn(v0.w)) << 16);
    o.z = ush(__float2half_rn(v1.x)) | ((unsigned)ush(__float2half_rn(v1.y)) << 16);
    o.w = ush(__float2half_rn(v1.z)) | ((unsigned)ush(__float2half_rn(v1.w)) << 16);
    return o;
}

__device__ __forceinline__ int win_token(int r) {
    int wid = r >> 6, n = r & 63;
    int b = wid >> 6, wy = (wid >> 3) & 7, wx = wid & 7;
    int h = wy * 8 + (n >> 3), w = wx * 8 + (n & 7);
    return (b << 12) + (h << 6) + w;
}

__device__ __forceinline__ uint32_t smem_u32(const void* p) {
    uint32_t a;
    asm("{ .reg .u64 t; cvta.to.shared.u64 t, %1; cvt.u32.u64 %0, t; }" : "=r"(a) : "l"(p));
    return a;
}
#define CP_ASYNC16(dst, src) \
    asm volatile("cp.async.cg.shared.global [%0], [%1], 16;" :: "r"(dst), "l"(src))
#define CP_COMMIT()  asm volatile("cp.async.commit_group;" ::: "memory")
#define CP_WAIT(n)   asm volatile("cp.async.wait_group %0;" :: "n"(n) : "memory")

// x -> fp16 single, WINDOWED row order
__global__ void split_x_kernel(const float* __restrict__ x) {
    int idx = blockIdx.x * 256 + threadIdx.x;
    int r = idx >> 6, c8 = idx & 63;
    int t = win_token(r);
    const float* src = x + (size_t)t * DIM + c8 * 8;
    float4 v0 = *reinterpret_cast<const float4*>(src);
    float4 v1 = *reinterpret_cast<const float4*>(src + 4);
    g_xh[idx] = pack8_fp16(v0, v1);
}

// weight matrix -> fp16 single (which: 0=qkv_w, 1=proj_w)
__global__ void split_w_kernel(const float* __restrict__ w, int which) {
    int idx = blockIdx.x * 256 + threadIdx.x;
    float4 v0 = *reinterpret_cast<const float4*>(w + (size_t)idx * 8);
    float4 v1 = *reinterpret_cast<const float4*>(w + (size_t)idx * 8 + 4);
    uint4* h = which ? g_wph : g_wqh;
    h[idx] = pack8_fp16(v0, v1);
}

// C = A @ W + bias; fp16 single-single, fp32 accum.
// 64x64 CTA tile, 128 threads, BK=64 double-buffered, ONE barrier per k-tile.
template<bool QKV>
__global__ void __launch_bounds__(128, 6)
gemm_kernel(const float* __restrict__ bias, float* __restrict__ out)
{
    constexpr int NCOLS = QKV ? NQKV : DIM;
    extern __shared__ __align__(16) char smraw[];
    __half* smb0 = reinterpret_cast<__half*>(smraw);
    const uint32_t sm_addr = smem_u32(smraw);
    __shared__ float2 rope[64];

    int tid  = threadIdx.x;
    int warp = tid >> 5;
    int wm = warp >> 1, wn = warp & 1;
    int rbase = blockIdx.x * BM;
    int nbase = blockIdx.y * BN;

    if (QKV && tid < 64) {
        int pos = tid >> 3, jj = tid & 7;
        float invf = exp2f(-1.6609640474436813f * (float)jj);  // 10000^(-jj/8)
        float sn, cs;
        sincosf((float)pos * invf, &sn, &cs);
        rope[tid] = make_float2(cs, sn);
    }

    // per-thread incrementing source pointers (row = (tid>>3)+s*16, col = tid&7)
    int prow = tid >> 3, pc = tid & 7;
    const uint4* asrc = (QKV ? g_xh  : g_aoh) + (size_t)(rbase + prow) * (DIM / 8) + pc;
    const uint4* bsrc = (QKV ? g_wqh : g_wph) + (size_t)prow * (NCOLS / 8) + nbase / 8 + pc;
    const size_t ARS = (size_t)16 * (DIM / 8);     // 16 A-rows
    const size_t BRS = (size_t)16 * (NCOLS / 8);   // 16 B-rows

    wmma::fragment<wmma::accumulator, 16, 16, 16, float> acc[2][2];
    #pragma unroll
    for (int i = 0; i < 2; i++)
        #pragma unroll
        for (int j = 0; j < 2; j++) wmma::fill_fragment(acc[i][j], 0.0f);

    auto issue = [&](int kt) {
        uint32_t st = sm_addr + (kt & 1) * STAGE_B;
        const uint4* a = asrc + kt * 8;
        #pragma unroll
        for (int s = 0; s < 4; s++)
            CP_ASYNC16(st + (prow + s * 16) * 144 + pc * 16, a + s * ARS);
        const uint4* b = bsrc + (size_t)kt * BK * (NCOLS / 8);
        #pragma unroll
        for (int s = 0; s < 4; s++)
            CP_ASYNC16(st + 9216 + (prow + s * 16) * 144 + pc * 16, b + s * BRS);
        CP_COMMIT();
    };

    issue(0);

    const int NKT = DIM / BK;   // 8
    for (int kt = 0; kt < NKT; kt++) {
        CP_WAIT(0);           // own copies for stage kt complete
        __syncthreads();      // everyone's copies visible; prev compute done
        if (kt + 1 < NKT) issue(kt + 1);   // overlaps with compute(kt)

        __half* smb = smb0 + (kt & 1) * STAGE_E;
        #pragma unroll
        for (int ks = 0; ks < 4; ks++) {
            wmma::fragment<wmma::matrix_a, 16, 16, 16, __half, wmma::row_major> fa[2];
            #pragma unroll
            for (int i = 0; i < 2; i++)
                wmma::load_matrix_sync(fa[i], smb + (wm * 32 + i * 16) * SA + ks * 16, SA);
            #pragma unroll
            for (int j = 0; j < 2; j++) {
                wmma::fragment<wmma::matrix_b, 16, 16, 16, __half, wmma::row_major> fb;
                int col = wn * 32 + j * 16;
                wmma::load_matrix_sync(fb, smb + 4608 + (ks * 16) * SB + col, SB);
                #pragma unroll
                for (int i = 0; i < 2; i++)
                    wmma::mma_sync(acc[i][j], fa[i], fb, acc[i][j]);
            }
        }
    }
    __syncthreads();
    float* csm = reinterpret_cast<float*>(smraw);
    #pragma unroll
    for (int i = 0; i < 2; i++)
        #pragma unroll
        for (int j = 0; j < 2; j++)
            wmma::store_matrix_sync(csm + (wm * 32 + i * 16) * SC + wn * 32 + j * 16,
                                    acc[i][j], SC, wmma::mem_row_major);
    __syncthreads();

    // Epilogue: 64x64 tile, 32 elems/thread; fused RoPE + plane split
    for (int s4 = 0; s4 < (BM * BN) / 128; s4++) {
        int idx = tid + s4 * 128;
        int i = idx >> 6, cl = idx & 63;
        int r = rbase + i;
        int c = nbase + cl;
        float v = csm[i * SC + cl] + bias[c];
        if (QKV) {
            int wid = r >> 6, n = r & 63;
            int which = c >> 9;           // 0=q 1=k 2=v
            int cc = c & 511;
            int head = cc >> 5, d = cc & 31;
            size_t di = (((size_t)wid * NH + head) * 64 + n) * HD + d;
            if (which < 2) {
                int j16 = d & 15;
                int g   = d >> 4;
                int pos = g ? (n & 7) : (n >> 3);
                float2 csn = rope[pos * 8 + (j16 & 7)];
                int off = (j16 < 8) ? 8 : -8;
                float vp = csm[i * SC + cl + off] + bias[c + off];
                float o = (j16 < 8) ? (v * csn.x - vp * csn.y) : (v * csn.x + vp * csn.y);
                if (which == 0) {
                    o *= WSCALE;
                    bf16 h = __float2bfloat16(o);
                    g_qh[di] = h;
                    g_ql[di] = __float2bfloat16(o - __bfloat162float(h));
                } else {
                    bf16 h = __float2bfloat16(o);
                    g_kh[di] = h;
                    g_kl[di] = __float2bfloat16(o - __bfloat162float(h));
                }
            } else {
                __half h = __float2half_rn(v);
                g_vh[di] = h;
                g_vl[di] = __float2half_rn(v - __half2float(h));
            }
        } else {
            int t = win_token(r);
            out[(size_t)t * DIM + c] = v;
        }
    }
}

// One CTA per (window, head): S = Q K^T (bf16-3, pre-split planes),
// softmax (fp16 A), O = A V (fp16-2). Output fp16 single for proj GEMM.
__global__ void attn_kernel()
{
    extern __shared__ __align__(16) char smraw[];
    bf16*   smb = reinterpret_cast<bf16*>(smraw);
    __half* smv = reinterpret_cast<__half*>(smraw);
    // 2B-elem offsets: qh 0, ql 2560, kh 5120, kl 7680, vh 10240, vl 12800
    float* s = reinterpret_cast<float*>(smraw + 30720);   // 64x68 f32
    __half* ah = smv;                                      // overlay 64x72 (dead q/k after S)

    int tid = threadIdx.x, warp = tid >> 5;
    int wid = blockIdx.x, head = blockIdx.y;
    size_t base = ((size_t)wid * NH + head) * (64 * HD);

    // load: 6 planes, pure uint4 copies (1 per thread per plane)
    {
        int row = tid >> 2, c4 = tid & 3;
        size_t go = base + row * 32 + c4 * 8;
        int so = row * ASA + c4 * 8;
        *reinterpret_cast<uint4*>(smb + so)         = *reinterpret_cast<const uint4*>(g_qh + go);
        *reinterpret_cast<uint4*>(smb + 2560 + so)  = *reinterpret_cast<const uint4*>(g_ql + go);
        *reinterpret_cast<uint4*>(smb + 5120 + so)  = *reinterpret_cast<const uint4*>(g_kh + go);
        *reinterpret_cast<uint4*>(smb + 7680 + so)  = *reinterpret_cast<const uint4*>(g_kl + go);
        *reinterpret_cast<uint4*>(smb + 10240 + so) = *reinterpret_cast<const uint4*>(g_vh + go);
        *reinterpret_cast<uint4*>(smb + 12800 + so) = *reinterpret_cast<const uint4*>(g_vl + go);
    }
    __syncthreads();

    // S = Q K^T : 16 frags of 16x16, 2 per warp (bf16-3)
    #pragma unroll
    for (int fi = 0; fi < 2; fi++) {
        int f = warp + fi * 8;
        int mi = f >> 2, ni = f & 3;
        wmma::fragment<wmma::accumulator, 16, 16, 16, float> acc;
        wmma::fill_fragment(acc, 0.0f);
        #pragma unroll
        for (int ks = 0; ks < 2; ks++) {
            wmma::fragment<wmma::matrix_a, 16, 16, 16, bf16, wmma::row_major> fah, fal;
            wmma::fragment<wmma::matrix_b, 16, 16, 16, bf16, wmma::col_major> fbh, fbl;
            wmma::load_matrix_sync(fah, smb + (mi * 16) * ASA + ks * 16, ASA);
            wmma::load_matrix_sync(fal, smb + 2560 + (mi * 16) * ASA + ks * 16, ASA);
            wmma::load_matrix_sync(fbh, smb + 5120 + (ni * 16) * ASA + ks * 16, ASA);
            wmma::load_matrix_sync(fbl, smb + 7680 + (ni * 16) * ASA + ks * 16, ASA);
            wmma::mma_sync(acc, fah, fbh, acc);
            wmma::mma_sync(acc, fah, fbl, acc);
            wmma::mma_sync(acc, fal, fbh, acc);
        }
        wmma::store_matrix_sync(s + (mi * 16) * SC + ni * 16, acc, SC, wmma::mem_row_major);
    }
    __syncthreads();

    // Row softmax: 4 threads per row, shfl reduce; A written as single fp16
    {
        int row = tid >> 2, l4 = tid & 3;
        float* sr = s + row * SC;
        float m = -1e30f;
        #pragma unroll
        for (int c = 0; c < 16; c++) m = fmaxf(m, sr[l4 * 16 + c]);
        m = fmaxf(m, __shfl_xor_sync(0xFFFFFFFF, m, 1));
        m = fmaxf(m, __shfl_xor_sync(0xFFFFFFFF, m, 2));
        float sum = 0.f;
        float e[16];
        #pragma unroll
        for (int c = 0; c < 16; c++) { e[c] = expf(sr[l4 * 16 + c] - m); sum += e[c]; }
        sum += __shfl_xor_sync(0xFFFFFFFF, sum, 1);
        sum += __shfl_xor_sync(0xFFFFFFFF, sum, 2);
        float inv = 1.f / sum;
        #pragma unroll
        for (int c = 0; c < 16; c++)
            ah[row * 72 + l4 * 16 + c] = __float2half_rn(e[c] * inv);
    }
    __syncthreads();

    // O = A V : fp16-2 (A single, V hi/lo); 8 frags (4x2), one per warp
    {
        int mi = warp >> 1, ni = warp & 1;
        wmma::fragment<wmma::accumulator, 16, 16, 16, float> acc;
        wmma::fill_fragment(acc, 0.0f);
        #pragma unroll
        for (int ks = 0; ks < 4; ks++) {
            wmma::fragment<wmma::matrix_a, 16, 16, 16, __half, wmma::row_major> fa;
            wmma::fragment<wmma::matrix_b, 16, 16, 16, __half, wmma::row_major> fbh, fbl;
            wmma::load_matrix_sync(fa, ah + (mi * 16) * 72 + ks * 16, 72);
            wmma::load_matrix_sync(fbh, smv + 10240 + (ks * 16) * ASA + ni * 16, ASA);
            wmma::load_matrix_sync(fbl, smv + 12800 + (ks * 16) * ASA + ni * 16, ASA);
            wmma::mma_sync(acc, fa, fbh, acc);
            wmma::mma_sync(acc, fa, fbl, acc);
        }
        wmma::store_matrix_sync(s + (mi * 16) * 36 + ni * 16, acc, 36, wmma::mem_row_major);
    }
    __syncthreads();

    // O -> g_aoh fp16 single (uint4 = 8 halves)
    {
        int row = tid >> 2, c8 = (tid & 3) * 8;
        float4 v0 = *reinterpret_cast<const float4*>(s + row * 36 + c8);
        float4 v1 = *reinterpret_cast<const float4*>(s + row * 36 + c8 + 4);
        size_t di = (size_t)(wid * 64 + row) * 64 + head * 4 + (tid & 3);
        g_aoh[di] = pack8_fp16(v0, v1);
    }
}

extern "C" void kernel_launch(void* const* d_in, const int* in_sizes, int n_in,
                              void* d_out, int out_size)
{
    (void)in_sizes; (void)n_in; (void)out_size;
    const float* x      = (const float*)d_in[0];
    const float* qkv_w  = (const float*)d_in[1];
    const float* qkv_b  = (const float*)d_in[2];
    // d_in[3], d_in[4] (kv_w, kv_b) are dead code in the reference output
    const float* proj_w = (const float*)d_in[5];
    const float* proj_b = (const float*)d_in[6];
    float* out = (float*)d_out;

    const int gemm_smem = 2 * STAGE_B;            // 36864 B (< 48KB default; csm 17408 fits)
    const int attn_smem = 30720 + 64 * SC * 4;    // 48128 B

    split_x_kernel<<<NTOK * DIM / 8 / 256, 256>>>(x);
    split_w_kernel<<<DIM * NQKV / 8 / 256, 256>>>(qkv_w, 0);
    split_w_kernel<<<DIM * DIM  / 8 / 256, 256>>>(proj_w, 1);

    gemm_kernel<true>
        <<<dim3(NTOK / BM, NQKV / BN), 128, gemm_smem>>>(qkv_b, nullptr);
    attn_kernel<<<dim3(NWIN, NH), 256, attn_smem>>>();
    gemm_kernel<false>
        <<<dim3(NTOK / BM, DIM / BN), 128, gemm_smem>>>(proj_b, out);
}

// round 17
// speedup vs baseline: 1.1028x; 1.1028x over previous
#include <cuda_runtime.h>
#include <cuda_bf16.h>
#include <cuda_fp16.h>
#include <mma.h>
#include <cstdint>

using namespace nvcuda;
typedef __nv_bfloat16 bf16;

#define DIM    512
#define NH     16
#define HD     32
#define NWIN   512      // 8 batches * 8*8 windows
#define NTOK   32768    // 512 windows * 64 tokens
#define NQKV   1536
#define WSCALE 0.17677669529663687f   // 32^-0.5

// GEMM tiling: 128x64 tile, 256 threads, BK=64, double-buffered,
// ONE barrier per k-tile. fp16 single-single, fp32 accum. (R15-proven 228us)
#define BM 128
#define BN 64
#define BK 64
#define SA 72    // A smem row stride (halves) — 144 B
#define SB 72    // B smem row stride (halves)
#define SC 68    // C epilogue stride (f32)
#define STAGE_B 27648          // bytes/stage: A 18432 + B 9216
#define STAGE_E 13824          // halves/stage
// attention smem stride
#define ASA 40

// Scratch (__device__ globals). RULE: referenced ONLY from device code.
// q/k/v: single fp16 planes (attention is all-fp16 single now).
__device__ __half g_qf[(size_t)NWIN * NH * 64 * HD];
__device__ __half g_kf[(size_t)NWIN * NH * 64 * HD];
__device__ __half g_vf[(size_t)NWIN * NH * 64 * HD];
// fp16 single-precision operands (uint4 = 8 halves)
__device__ uint4 g_xh [(size_t)NTOK * DIM / 8];
__device__ uint4 g_aoh[(size_t)NTOK * DIM / 8];
__device__ uint4 g_wqh[(size_t)DIM * NQKV / 8];
__device__ uint4 g_wph[(size_t)DIM * DIM / 8];

__device__ __forceinline__ unsigned short ush(__half v) { return __half_as_ushort(v); }

__device__ __forceinline__ uint4 pack8_fp16(float4 v0, float4 v1) {
    uint4 o;
    o.x = ush(__float2half_rn(v0.x)) | ((unsigned)ush(__float2half_rn(v0.y)) << 16);
    o.y = ush(__float2half_rn(v0.z)) | ((unsigned)ush(__float2half_rn(v0.w)) << 16);
    o.z = ush(__float2half_rn(v1.x)) | ((unsigned)ush(__float2half_rn(v1.y)) << 16);
    o.w = ush(__float2half_rn(v1.z)) | ((unsigned)ush(__float2half_rn(v1.w)) << 16);
    return o;
}

__device__ __forceinline__ int win_token(int r) {
    int wid = r >> 6, n = r & 63;
    int b = wid >> 6, wy = (wid >> 3) & 7, wx = wid & 7;
    int h = wy * 8 + (n >> 3), w = wx * 8 + (n & 7);
    return (b << 12) + (h << 6) + w;
}

__device__ __forceinline__ uint32_t smem_u32(const void* p) {
    uint32_t a;
    asm("{ .reg .u64 t; cvta.to.shared.u64 t, %1; cvt.u32.u64 %0, t; }" : "=r"(a) : "l"(p));
    return a;
}
#define CP_ASYNC16(dst, src) \
    asm volatile("cp.async.cg.shared.global [%0], [%1], 16;" :: "r"(dst), "l"(src))
#define CP_COMMIT()  asm volatile("cp.async.commit_group;" ::: "memory")
#define CP_WAIT(n)   asm volatile("cp.async.wait_group %0;" :: "n"(n) : "memory")

// x -> fp16 single, WINDOWED row order
__global__ void split_x_kernel(const float* __restrict__ x) {
    int idx = blockIdx.x * 256 + threadIdx.x;
    int r = idx >> 6, c8 = idx & 63;
    int t = win_token(r);
    const float* src = x + (size_t)t * DIM + c8 * 8;
    float4 v0 = *reinterpret_cast<const float4*>(src);
    float4 v1 = *reinterpret_cast<const float4*>(src + 4);
    g_xh[idx] = pack8_fp16(v0, v1);
}

// weight matrix -> fp16 single (which: 0=qkv_w, 1=proj_w)
__global__ void split_w_kernel(const float* __restrict__ w, int which) {
    int idx = blockIdx.x * 256 + threadIdx.x;
    float4 v0 = *reinterpret_cast<const float4*>(w + (size_t)idx * 8);
    float4 v1 = *reinterpret_cast<const float4*>(w + (size_t)idx * 8 + 4);
    uint4* h = which ? g_wph : g_wqh;
    h[idx] = pack8_fp16(v0, v1);
}

// C = A @ W + bias; fp16 single-single, fp32 accum.
// BK=64 double-buffered cp.async, ONE barrier per k-tile.
template<bool QKV>
__global__ void __launch_bounds__(256, 3)
gemm_kernel(const float* __restrict__ bias, float* __restrict__ out)
{
    constexpr int NCOLS = QKV ? NQKV : DIM;
    extern __shared__ __align__(16) char smraw[];
    __half* smb0 = reinterpret_cast<__half*>(smraw);
    const uint32_t sm_addr = smem_u32(smraw);
    __shared__ float2 rope[64];

    int tid  = threadIdx.x;
    int warp = tid >> 5;
    int wm = warp >> 1, wn = warp & 1;
    int rbase = blockIdx.x * BM;
    int nbase = blockIdx.y * BN;

    if (QKV && tid < 64) {
        int pos = tid >> 3, jj = tid & 7;
        float invf = exp2f(-1.6609640474436813f * (float)jj);  // 10000^(-jj/8)
        float sn, cs;
        sincosf((float)pos * invf, &sn, &cs);
        rope[tid] = make_float2(cs, sn);
    }

    // per-thread incrementing source pointers
    int arow = tid >> 3, ac = tid & 7;           // A: 128x8, 4 chunks/thread (rows +32)
    int brow = tid >> 3, bc = tid & 7;           // B: 64x8,  2 chunks/thread (rows +32)
    const uint4* asrc = (QKV ? g_xh  : g_aoh) + (size_t)(rbase + arow) * (DIM / 8) + ac;
    const uint4* bsrc = (QKV ? g_wqh : g_wph) + (size_t)brow * (NCOLS / 8) + nbase / 8 + bc;
    const size_t ARS = (size_t)32 * (DIM / 8);     // 32 A-rows
    const size_t BRS = (size_t)32 * (NCOLS / 8);   // 32 B-rows

    wmma::fragment<wmma::accumulator, 16, 16, 16, float> acc[2][2];
    #pragma unroll
    for (int i = 0; i < 2; i++)
        #pragma unroll
        for (int j = 0; j < 2; j++) wmma::fill_fragment(acc[i][j], 0.0f);

    auto issue = [&](int kt) {
        uint32_t st = sm_addr + (kt & 1) * STAGE_B;
        const uint4* a = asrc + kt * 8;
        #pragma unroll
        for (int s = 0; s < 4; s++)
            CP_ASYNC16(st + (arow + s * 32) * 144 + ac * 16, a + s * ARS);
        const uint4* b = bsrc + (size_t)kt * BK * (NCOLS / 8);
        #pragma unroll
        for (int s = 0; s < 2; s++)
            CP_ASYNC16(st + 18432 + (brow + s * 32) * 144 + bc * 16, b + s * BRS);
        CP_COMMIT();
    };

    issue(0);

    const int NKT = DIM / BK;   // 8
    for (int kt = 0; kt < NKT; kt++) {
        CP_WAIT(0);           // own copies for stage kt complete
        __syncthreads();      // everyone's copies visible; prev compute done
        if (kt + 1 < NKT) issue(kt + 1);   // overlaps with compute(kt)

        __half* smb = smb0 + (kt & 1) * STAGE_E;
        #pragma unroll
        for (int ks = 0; ks < 4; ks++) {
            wmma::fragment<wmma::matrix_a, 16, 16, 16, __half, wmma::row_major> fa[2];
            #pragma unroll
            for (int i = 0; i < 2; i++)
                wmma::load_matrix_sync(fa[i], smb + (wm * 32 + i * 16) * SA + ks * 16, SA);
            #pragma unroll
            for (int j = 0; j < 2; j++) {
                wmma::fragment<wmma::matrix_b, 16, 16, 16, __half, wmma::row_major> fb;
                int col = wn * 32 + j * 16;
                wmma::load_matrix_sync(fb, smb + 9216 + (ks * 16) * SB + col, SB);
                #pragma unroll
                for (int i = 0; i < 2; i++)
                    wmma::mma_sync(acc[i][j], fa[i], fb, acc[i][j]);
            }
        }
    }
    __syncthreads();
    float* csm = reinterpret_cast<float*>(smraw);
    #pragma unroll
    for (int i = 0; i < 2; i++)
        #pragma unroll
        for (int j = 0; j < 2; j++)
            wmma::store_matrix_sync(csm + (wm * 32 + i * 16) * SC + wn * 32 + j * 16,
                                    acc[i][j], SC, wmma::mem_row_major);
    __syncthreads();

    // Epilogue: 128x64 tile, 32 elems/thread; fused RoPE, single fp16 planes
    for (int s4 = 0; s4 < (BM * BN) / 256; s4++) {
        int idx = tid + s4 * 256;
        int i = idx >> 6, cl = idx & 63;
        int r = rbase + i;
        int c = nbase + cl;
        float v = csm[i * SC + cl] + bias[c];
        if (QKV) {
            int wid = r >> 6, n = r & 63;
            int which = c >> 9;           // 0=q 1=k 2=v
            int cc = c & 511;
            int head = cc >> 5, d = cc & 31;
            size_t di = (((size_t)wid * NH + head) * 64 + n) * HD + d;
            if (which < 2) {
                int j16 = d & 15;
                int g   = d >> 4;
                int pos = g ? (n & 7) : (n >> 3);
                float2 csn = rope[pos * 8 + (j16 & 7)];
                int off = (j16 < 8) ? 8 : -8;
                float vp = csm[i * SC + cl + off] + bias[c + off];
                float o = (j16 < 8) ? (v * csn.x - vp * csn.y) : (v * csn.x + vp * csn.y);
                if (which == 0) g_qf[di] = __float2half_rn(o * WSCALE);
                else            g_kf[di] = __float2half_rn(o);
            } else {
                g_vf[di] = __float2half_rn(v);
            }
        } else {
            int t = win_token(r);
            out[(size_t)t * DIM + c] = v;
        }
    }
}

// One CTA per (window, head): all-fp16-single attention.
// S = Q K^T (1 MMA/frag), softmax, O = A V (1 MMA/frag). Output fp16 single.
__global__ void attn_kernel()
{
    extern __shared__ __align__(16) char smraw[];
    __half* smv = reinterpret_cast<__half*>(smraw);
    // halves offsets: q 0, k 2560, v 5120 (each 64 rows x ASA)
    float* s = reinterpret_cast<float*>(smraw + 15360);   // 64x68 f32 (17408 B)
    __half* ah = smv;                                      // overlay 64x72 over q+k

    int tid = threadIdx.x, warp = tid >> 5;
    int wid = blockIdx.x, head = blockIdx.y;
    size_t base = ((size_t)wid * NH + head) * (64 * HD);

    // load: 3 planes, pure uint4 copies (1 per thread per plane)
    {
        int row = tid >> 2, c4 = tid & 3;
        size_t go = base + row * 32 + c4 * 8;
        int so = row * ASA + c4 * 8;
        *reinterpret_cast<uint4*>(smv + so)        = *reinterpret_cast<const uint4*>(g_qf + go);
        *reinterpret_cast<uint4*>(smv + 2560 + so) = *reinterpret_cast<const uint4*>(g_kf + go);
        *reinterpret_cast<uint4*>(smv + 5120 + so) = *reinterpret_cast<const uint4*>(g_vf + go);
    }
    __syncthreads();

    // S = Q K^T : 16 frags of 16x16, 2 per warp (fp16 single)
    #pragma unroll
    for (int fi = 0; fi < 2; fi++) {
        int f = warp + fi * 8;
        int mi = f >> 2, ni = f & 3;
        wmma::fragment<wmma::accumulator, 16, 16, 16, float> acc;
        wmma::fill_fragment(acc, 0.0f);
        #pragma unroll
        for (int ks = 0; ks < 2; ks++) {
            wmma::fragment<wmma::matrix_a, 16, 16, 16, __half, wmma::row_major> fa;
            wmma::fragment<wmma::matrix_b, 16, 16, 16, __half, wmma::col_major> fb;
            wmma::load_matrix_sync(fa, smv + (mi * 16) * ASA + ks * 16, ASA);
            wmma::load_matrix_sync(fb, smv + 2560 + (ni * 16) * ASA + ks * 16, ASA);
            wmma::mma_sync(acc, fa, fb, acc);
        }
        wmma::store_matrix_sync(s + (mi * 16) * SC + ni * 16, acc, SC, wmma::mem_row_major);
    }
    __syncthreads();

    // Row softmax: 4 threads per row, shfl reduce; A written as single fp16
    {
        int row = tid >> 2, l4 = tid & 3;
        float* sr = s + row * SC;
        float m = -1e30f;
        #pragma unroll
        for (int c = 0; c < 16; c++) m = fmaxf(m, sr[l4 * 16 + c]);
        m = fmaxf(m, __shfl_xor_sync(0xFFFFFFFF, m, 1));
        m = fmaxf(m, __shfl_xor_sync(0xFFFFFFFF, m, 2));
        float sum = 0.f;
        float e[16];
        #pragma unroll
        for (int c = 0; c < 16; c++) { e[c] = expf(sr[l4 * 16 + c] - m); sum += e[c]; }
        sum += __shfl_xor_sync(0xFFFFFFFF, sum, 1);
        sum += __shfl_xor_sync(0xFFFFFFFF, sum, 2);
        float inv = 1.f / sum;
        #pragma unroll
        for (int c = 0; c < 16; c++)
            ah[row * 72 + l4 * 16 + c] = __float2half_rn(e[c] * inv);
    }
    __syncthreads();

    // O = A V : fp16 single; 8 frags (4x2), one per warp
    {
        int mi = warp >> 1, ni = warp & 1;
        wmma::fragment<wmma::accumulator, 16, 16, 16, float> acc;
        wmma::fill_fragment(acc, 0.0f);
        #pragma unroll
        for (int ks = 0; ks < 4; ks++) {
            wmma::fragment<wmma::matrix_a, 16, 16, 16, __half, wmma::row_major> fa;
            wmma::fragment<wmma::matrix_b, 16, 16, 16, __half, wmma::row_major> fb;
            wmma::load_matrix_sync(fa, ah + (mi * 16) * 72 + ks * 16, 72);
            wmma::load_matrix_sync(fb, smv + 5120 + (ks * 16) * ASA + ni * 16, ASA);
            wmma::mma_sync(acc, fa, fb, acc);
        }
        wmma::store_matrix_sync(s + (mi * 16) * 36 + ni * 16, acc, 36, wmma::mem_row_major);
    }
    __syncthreads();

    // O -> g_aoh fp16 single (uint4 = 8 halves)
    {
        int row = tid >> 2, c8 = (tid & 3) * 8;
        float4 v0 = *reinterpret_cast<const float4*>(s + row * 36 + c8);
        float4 v1 = *reinterpret_cast<const float4*>(s + row * 36 + c8 + 4);
        size_t di = (size_t)(wid * 64 + row) * 64 + head * 4 + (tid & 3);
        g_aoh[di] = pack8_fp16(v0, v1);
    }
}

extern "C" void kernel_launch(void* const* d_in, const int* in_sizes, int n_in,
                              void* d_out, int out_size)
{
    (void)in_sizes; (void)n_in; (void)out_size;
    const float* x      = (const float*)d_in[0];
    const float* qkv_w  = (const float*)d_in[1];
    const float* qkv_b  = (const float*)d_in[2];
    // d_in[3], d_in[4] (kv_w, kv_b) are dead code in the reference output
    const float* proj_w = (const float*)d_in[5];
    const float* proj_b = (const float*)d_in[6];
    float* out = (float*)d_out;

    const int gemm_smem = 2 * STAGE_B;            // 55296 B (csm 34816 fits)
    const int attn_smem = 15360 + 64 * SC * 4;    // 32768 B

    cudaFuncSetAttribute(gemm_kernel<true>,
                         cudaFuncAttributeMaxDynamicSharedMemorySize, gemm_smem);
    cudaFuncSetAttribute(gemm_kernel<false>,
                         cudaFuncAttributeMaxDynamicSharedMemorySize, gemm_smem);

    split_x_kernel<<<NTOK * DIM / 8 / 256, 256>>>(x);
    split_w_kernel<<<DIM * NQKV / 8 / 256, 256>>>(qkv_w, 0);
    split_w_kernel<<<DIM * DIM  / 8 / 256, 256>>>(proj_w, 1);

    gemm_kernel<true>
        <<<dim3(NTOK / BM, NQKV / BN), 256, gemm_smem>>>(qkv_b, nullptr);
    attn_kernel<<<dim3(NWIN, NH), 256, attn_smem>>>();
    gemm_kernel<false>
        <<<dim3(NTOK / BM, DIM / BN), 256, gemm_smem>>>(proj_b, out);
}